// round 4
// baseline (speedup 1.0000x reference)
#include <cuda_runtime.h>
#include <math.h>

// Problem constants
#define BQ 16
#define TQ 256
#define DQ 512
#define HQ 256
#define KQ 20
#define MR (BQ*TQ)          // 4096 rows
#define NB_DIR 64           // persistent blocks per LSTM direction

// ---------------- device scratch (no runtime allocation allowed) ----------------
__device__ float g_e [MR*DQ];        // embedding out / layer-0 input
__device__ float g_l0[MR*DQ];        // layer-0 bilstm output
__device__ float g_l1[MR*DQ];        // layer-1 bilstm output (residual source)
__device__ float g_t [MR*DQ];        // ff temp (relu)
__device__ float g_f [MR*DQ];        // ff temp
__device__ float g_ho[MR*HQ];        // ffo output
__device__ float g_xw[MR*2048];      // precomputed input-gate activations (both dirs)
__device__ float g_h [2][2][BQ][HQ]; // [dir][pingpong][batch][hidden]
__device__ unsigned g_bar[2];        // per-direction barrier counters

// ---------------- embedding gather ----------------
__global__ void k_embed(const int* __restrict__ x, const float* __restrict__ emb,
                        float* __restrict__ out)
{
    int row = blockIdx.x;                       // b*T + t
    int tok = x[row];
    const float4* src = (const float4*)(emb + (size_t)tok * DQ);
    float4*       dst = (float4*)(out + (size_t)row * DQ);
    for (int i = threadIdx.x; i < DQ/4; i += blockDim.x) dst[i] = src[i];
}

// ---------------- SGEMM: C[M,N] = A[M,K] * W[N,K]^T + bias (NT, fp32) ----------------
// 128x128 tile, BK=8, 256 threads, 8x8 micro-tile, float4 frags.
template<int RELU, int RES>
__global__ __launch_bounds__(256, 2)
void k_gemm_nt(const float* __restrict__ A, const float* __restrict__ W,
               const float* __restrict__ bias, const float* __restrict__ res,
               float* __restrict__ C, int M, int N, int K)
{
    __shared__ float As[8][128];
    __shared__ float Bs[8][128];

    const int tid = threadIdx.x;
    const int bm  = blockIdx.y * 128;
    const int bn  = blockIdx.x * 128;

    const int lr = tid >> 1;            // 0..127
    const int lk = (tid & 1) << 2;      // 0 or 4

    const float* Ag = A + (size_t)(bm + lr) * K + lk;
    const float* Wg = W + (size_t)(bn + lr) * K + lk;

    const int tx = tid & 15;            // 0..15
    const int ty = tid >> 4;            // 0..15

    float acc[8][8];
#pragma unroll
    for (int i = 0; i < 8; i++)
#pragma unroll
        for (int j = 0; j < 8; j++) acc[i][j] = 0.f;

    float4 ra = *(const float4*)Ag;
    float4 rw = *(const float4*)Wg;

    const int nIter = K >> 3;
    for (int it = 0; it < nIter; ++it) {
        As[lk+0][lr] = ra.x; As[lk+1][lr] = ra.y; As[lk+2][lr] = ra.z; As[lk+3][lr] = ra.w;
        Bs[lk+0][lr] = rw.x; Bs[lk+1][lr] = rw.y; Bs[lk+2][lr] = rw.z; Bs[lk+3][lr] = rw.w;
        __syncthreads();
        if (it + 1 < nIter) {
            ra = *(const float4*)(Ag + (size_t)(it+1) * 8);
            rw = *(const float4*)(Wg + (size_t)(it+1) * 8);
        }
#pragma unroll
        for (int kk = 0; kk < 8; ++kk) {
            float af[8], bf[8];
            *(float4*)&af[0] = *(const float4*)&As[kk][ty*4];
            *(float4*)&af[4] = *(const float4*)&As[kk][64 + ty*4];
            *(float4*)&bf[0] = *(const float4*)&Bs[kk][tx*4];
            *(float4*)&bf[4] = *(const float4*)&Bs[kk][64 + tx*4];
#pragma unroll
            for (int i = 0; i < 8; i++)
#pragma unroll
                for (int j = 0; j < 8; j++)
                    acc[i][j] = fmaf(af[i], bf[j], acc[i][j]);
        }
        __syncthreads();
    }

    // epilogue (vectorized, coalesced)
#pragma unroll
    for (int ih = 0; ih < 2; ih++) {
#pragma unroll
        for (int ii = 0; ii < 4; ii++) {
            int m = bm + ih*64 + ty*4 + ii;
            float* crow = C + (size_t)m * N;
#pragma unroll
            for (int jh = 0; jh < 2; jh++) {
                int n = bn + jh*64 + tx*4;
                float4 bv = *(const float4*)&bias[n];
                float4 v;
                v.x = acc[ih*4+ii][jh*4+0] + bv.x;
                v.y = acc[ih*4+ii][jh*4+1] + bv.y;
                v.z = acc[ih*4+ii][jh*4+2] + bv.z;
                v.w = acc[ih*4+ii][jh*4+3] + bv.w;
                if (RELU) {
                    v.x = fmaxf(v.x, 0.f); v.y = fmaxf(v.y, 0.f);
                    v.z = fmaxf(v.z, 0.f); v.w = fmaxf(v.w, 0.f);
                }
                if (RES) {
                    float4 rv = *(const float4*)(res + (size_t)m * N + n);
                    v.x += rv.x; v.y += rv.y; v.z += rv.z; v.w += rv.w;
                }
                *(float4*)&crow[n] = v;
            }
        }
    }
}

// ---------------- persistent bidirectional LSTM recurrence (one layer) ----------------
// grid = 128 blocks: [0,64) fwd, [64,128) bwd. Each block owns 4 hidden units
// (16 gate-rows), Whh slice cached in smem, h exchanged via L2 + atomic barrier.
__device__ __forceinline__ float sigf(float x) { return 1.f / (1.f + __expf(-x)); }

__global__ __launch_bounds__(256, 1)
void k_lstm(const float* __restrict__ xw,   // [4096][2048] (dir*1024 + gate*256 + j)
            const float* __restrict__ Whh,  // [2][1024][256] for this layer
            float* __restrict__ out)        // [4096][512], col = dir*256 + j
{
    __shared__ float Wsh[16][260];
    __shared__ float hsh[16][260];
    __shared__ float gsh[4][4][16];   // [gate][j_local][batch]
    __shared__ float csh[4][16];

    const int blk = blockIdx.x;
    const int dir = blk >> 6;
    const int bb  = blk & 63;
    const int j0  = bb * 4;
    const int tid = threadIdx.x;

    const int rl   = tid >> 4;        // 0..15 local gate-row
    const int b    = tid & 15;        // batch
    const int gate = rl >> 2;
    const int jl   = rl & 3;
    const int grow = gate * 256 + j0 + jl;   // global gate row in [0,1024)

    // load Whh slice (16 rows x 256) into smem once
    const float* Wd = Whh + (size_t)dir * 1024 * 256;
    for (int idx = tid; idx < 16 * 256; idx += 256) {
        int r = idx >> 8, k = idx & 255;
        int gg = r >> 2, jj = r & 3;
        Wsh[r][k] = Wd[(size_t)(gg * 256 + j0 + jj) * 256 + k];
    }
    if (tid < 64) csh[tid >> 4][tid & 15] = 0.f;
    __syncthreads();

    for (int s = 0; s < 256; ++s) {
        const int t = dir ? (255 - s) : s;

        // issue xw load early (overlaps with staging)
        float xv = __ldg(&xw[((size_t)(b * TQ + t)) * 2048 + dir * 1024 + grow]);

        // stage h_prev into smem
        if (s == 0) {
            for (int i = tid; i < 16 * 64; i += 256) {
                int b2 = i >> 6, k4 = (i & 63) << 2;
                *(float4*)&hsh[b2][k4] = make_float4(0.f, 0.f, 0.f, 0.f);
            }
        } else {
            const float4* hp = (const float4*)&g_h[dir][(s - 1) & 1][0][0];
#pragma unroll
            for (int r = 0; r < 4; r++) {
                int i = tid + r * 256;
                float4 v = __ldcg(hp + i);            // bypass L1 (cross-block data)
                int b2 = i >> 6, k4 = (i & 63) << 2;
                *(float4*)&hsh[b2][k4] = v;
            }
        }
        __syncthreads();

        // dot product: gate[grow][b] = xw + Whh_row . h[b]
        float a0 = 0.f, a1 = 0.f, a2 = 0.f, a3 = 0.f;
        const float* wr = &Wsh[rl][0];
        const float* hr = &hsh[b][0];
#pragma unroll
        for (int k = 0; k < 256; k += 8) {
            float4 w0 = *(const float4*)(wr + k);
            float4 h0 = *(const float4*)(hr + k);
            float4 w1 = *(const float4*)(wr + k + 4);
            float4 h1 = *(const float4*)(hr + k + 4);
            a0 = fmaf(w0.x, h0.x, a0); a1 = fmaf(w0.y, h0.y, a1);
            a2 = fmaf(w0.z, h0.z, a2); a3 = fmaf(w0.w, h0.w, a3);
            a0 = fmaf(w1.x, h1.x, a0); a1 = fmaf(w1.y, h1.y, a1);
            a2 = fmaf(w1.z, h1.z, a2); a3 = fmaf(w1.w, h1.w, a3);
        }
        gsh[gate][jl][b] = xv + ((a0 + a1) + (a2 + a3));
        __syncthreads();

        // combine gates -> c, h  (64 threads: rl<4 acts as j_local)
        if (rl < 4) {
            float iv = gsh[0][rl][b];
            float fv = gsh[1][rl][b];
            float gv = gsh[2][rl][b];
            float ov = gsh[3][rl][b];
            float c  = sigf(fv) * csh[rl][b] + sigf(iv) * tanhf(gv);
            csh[rl][b] = c;
            float h  = sigf(ov) * tanhf(c);
            g_h[dir][s & 1][b][j0 + rl] = h;
            out[((size_t)(b * TQ + t)) * DQ + dir * HQ + j0 + rl] = h;
        }

        if (s < 255) {
            __threadfence();
            __syncthreads();
            if (tid == 0) {
                atomicAdd(&g_bar[dir], 1u);
                const unsigned target = (unsigned)(s + 1) * NB_DIR;
                volatile unsigned* p = &g_bar[dir];
                while (*p < target) { }
            }
            __syncthreads();
        }
    }
}

// ---------------- emissions: em = ho(4096x256) @ out_W(20x256)^T + out_b ----------------
__global__ void k_emout(const float* __restrict__ ho, const float* __restrict__ Wo,
                        const float* __restrict__ bo, float* __restrict__ em)
{
    __shared__ float Ws[KQ * HQ];
    for (int i = threadIdx.x; i < KQ * HQ; i += blockDim.x) Ws[i] = Wo[i];
    __syncthreads();
    int m0 = blockIdx.x * 64;
    for (int idx = threadIdx.x; idx < 64 * KQ; idx += blockDim.x) {
        int mi = idx / KQ, n = idx % KQ;
        const float* a = ho + (size_t)(m0 + mi) * HQ;
        const float* w = Ws + n * HQ;
        float s0 = 0.f, s1 = 0.f, s2 = 0.f, s3 = 0.f;
#pragma unroll
        for (int k = 0; k < HQ; k += 4) {
            float4 av = __ldg((const float4*)(a + k));
            float4 wv = *(const float4*)(w + k);
            s0 = fmaf(av.x, wv.x, s0); s1 = fmaf(av.y, wv.y, s1);
            s2 = fmaf(av.z, wv.z, s2); s3 = fmaf(av.w, wv.w, s3);
        }
        em[(size_t)(m0 + mi) * KQ + n] = bo[n] + ((s0 + s1) + (s2 + s3));
    }
}

// ---------------- Viterbi decode: one block (warp) per batch ----------------
__global__ void k_viterbi(const float* __restrict__ em, const float* __restrict__ start,
                          const float* __restrict__ endw, const float* __restrict__ trans,
                          float* __restrict__ tagout)
{
    __shared__ float sc[2][KQ];
    __shared__ float tr[KQ * KQ];
    __shared__ unsigned char hist[TQ - 1][KQ];

    const int bq = blockIdx.x;
    const int tj = threadIdx.x;
    for (int i = tj; i < KQ * KQ; i += 32) tr[i] = trans[i];
    const float* e = em + (size_t)bq * TQ * KQ;
    if (tj < KQ) sc[0][tj] = start[tj] + e[tj];
    __syncwarp();

    for (int t = 1; t < TQ; ++t) {
        if (tj < KQ) {
            const float* sp = sc[(t - 1) & 1];
            float best = -3.4e38f; int bi = 0;
#pragma unroll
            for (int i = 0; i < KQ; ++i) {
                float v = sp[i] + tr[i * KQ + tj];
                if (v > best) { best = v; bi = i; }   // first-max like jnp.argmax
            }
            sc[t & 1][tj] = best + e[(size_t)t * KQ + tj];
            hist[t - 1][tj] = (unsigned char)bi;
        }
        __syncwarp();
    }

    if (tj == 0) {
        float best = -3.4e38f; int tag = 0;
        for (int j = 0; j < KQ; ++j) {
            float v = sc[(TQ - 1) & 1][j] + endw[j];
            if (v > best) { best = v; tag = j; }
        }
        float* to = tagout + (size_t)bq * TQ;
        to[TQ - 1] = (float)tag;
        for (int t = TQ - 2; t >= 0; --t) {
            tag = hist[t][tag];
            to[t] = (float)tag;
        }
    }
}

// ---------------- launcher (graph-capturable: launches + memset only) ----------------
extern "C" void kernel_launch(void* const* d_in, const int* in_sizes, int n_in,
                              void* d_out, int out_size)
{
    const int*   x    = (const int*)  d_in[0];
    const float* emb  = (const float*)d_in[1];
    const float* Wih  = (const float*)d_in[2];   // (2,2,1024,512)
    const float* Whh  = (const float*)d_in[3];   // (2,2,1024,256)
    const float* lb   = (const float*)d_in[4];   // (2,2,1024)
    const float* fW1  = (const float*)d_in[5];   // (2,512,512)
    const float* fb1  = (const float*)d_in[6];
    const float* fW2  = (const float*)d_in[7];
    const float* fb2  = (const float*)d_in[8];
    const float* foW  = (const float*)d_in[9];   // (256,512)
    const float* fob  = (const float*)d_in[10];
    const float* oW   = (const float*)d_in[11];  // (20,256)
    const float* ob   = (const float*)d_in[12];
    const float* cs   = (const float*)d_in[13];
    const float* ce   = (const float*)d_in[14];
    const float* ct   = (const float*)d_in[15];
    float* out = (float*)d_out;

    float *p_e, *p_l0, *p_l1, *p_t, *p_f, *p_ho, *p_xw; void* p_bar;
    cudaGetSymbolAddress((void**)&p_e,  g_e);
    cudaGetSymbolAddress((void**)&p_l0, g_l0);
    cudaGetSymbolAddress((void**)&p_l1, g_l1);
    cudaGetSymbolAddress((void**)&p_t,  g_t);
    cudaGetSymbolAddress((void**)&p_f,  g_f);
    cudaGetSymbolAddress((void**)&p_ho, g_ho);
    cudaGetSymbolAddress((void**)&p_xw, g_xw);
    cudaGetSymbolAddress(&p_bar, g_bar);

    // 1. embedding
    k_embed<<<MR, 128>>>(x, emb, p_e);

    // 2. layer 0: xw GEMM (N covers both directions: 2048 rows of Wih[0])
    k_gemm_nt<0,0><<<dim3(2048/128, MR/128), 256>>>(p_e, Wih, lb, nullptr, p_xw, MR, 2048, 512);
    cudaMemsetAsync(p_bar, 0, 2 * sizeof(unsigned));
    k_lstm<<<2 * NB_DIR, 256>>>(p_xw, Whh, p_l0);

    // 3. layer 1
    k_gemm_nt<0,0><<<dim3(2048/128, MR/128), 256>>>(p_l0, Wih + (size_t)2*1024*512,
                                                    lb + 2048, nullptr, p_xw, MR, 2048, 512);
    cudaMemsetAsync(p_bar, 0, 2 * sizeof(unsigned));
    k_lstm<<<2 * NB_DIR, 256>>>(p_xw, Whh + (size_t)2*1024*256, p_l1);

    // 4. feedforward blocks (residual added in the last GEMM)
    k_gemm_nt<1,0><<<dim3(512/128, MR/128), 256>>>(p_l1, fW1, fb1, nullptr, p_t, MR, 512, 512);
    k_gemm_nt<0,0><<<dim3(512/128, MR/128), 256>>>(p_t,  fW2, fb2, nullptr, p_f, MR, 512, 512);
    k_gemm_nt<1,0><<<dim3(512/128, MR/128), 256>>>(p_f,  fW1 + 512*512, fb1 + 512, nullptr, p_t, MR, 512, 512);
    k_gemm_nt<0,1><<<dim3(512/128, MR/128), 256>>>(p_t,  fW2 + 512*512, fb2 + 512, p_l1, p_f, MR, 512, 512);

    // 5. output projections
    k_gemm_nt<0,0><<<dim3(256/128, MR/128), 256>>>(p_f, foW, fob, nullptr, p_ho, MR, 256, 512);
    k_emout<<<MR/64, 256>>>(p_ho, oW, ob, out);

    // 6. Viterbi tags appended after em (as float), if the output holds them
    if (out_size >= MR * KQ + MR) {
        k_viterbi<<<BQ, 32>>>(out, cs, ce, ct, out + MR * KQ);
    }
}